// round 8
// baseline (speedup 1.0000x reference)
#include <cuda_runtime.h>
#include <cstdint>

#define B_   64
#define T_   1152
#define C_   64
#define F_   8
#define KH_  32
#define PAD_ 15
#define TTILE 16

typedef unsigned long long ull;

// ---------------- scratch (device globals; no allocation allowed) ----------
__device__ float g_snn[(size_t)B_ * T_ * 32];           // snn_in (B,T,32)  ~9.4 MB
__device__ int   g_cnt[B_];                             // per-batch spike counts
__device__ int   g_done = 0;                            // completion ticket

// ---------------- f32x2 helpers (sm_100+) ----------------------------------
__device__ __forceinline__ ull pack_dup(float x) {
    unsigned int xi = __float_as_uint(x);
    ull r;
    asm("mov.b64 %0, {%1, %1};" : "=l"(r) : "r"(xi));
    return r;
}
__device__ __forceinline__ ull fma2(ull a, ull b, ull c) {
    ull d;
    asm("fma.rn.f32x2 %0, %1, %2, %3;" : "=l"(d) : "l"(a), "l"(b), "l"(c));
    return d;
}
__device__ __forceinline__ void unpack2(ull v, float& lo, float& hi) {
    unsigned int l, h;
    asm("mov.b64 {%0, %1}, %2;" : "=r"(l), "=r"(h) : "l"(v));
    lo = __uint_as_float(l);
    hi = __uint_as_float(h);
}

// ---------------- K1: conv(32 taps) + LN + ReLU + M-projection -------------
// grid (T/16, B), block 256: tid = c (0..63) + 64*g (g=0..3); each thread does
// 4 consecutive timesteps via a rolling 4-row register window (f32x2-dup'd).
// Invariant: at the start of tap kh, slot (r & 3) holds relative row r for
// r in [kh, kh+3]; output tt at tap kh consumes row kh+tt. Rows run to
// kh_max + tt_max = 34, hence refills continue while kh < 31.
// The folded projection matrix M[s][c] = sum_c' spw[c'][s] * L[b][c'][c] is
// computed in-block (one element per thread).
__global__ void __launch_bounds__(256)
k1_conv(const float* __restrict__ X, const float* __restrict__ Kg,
        const float* __restrict__ lnS, const float* __restrict__ lnB,
        const float* __restrict__ Ln, const float* __restrict__ spw) {
    __shared__ __align__(16) ull sK2[1024];  // conv kernel f32x2 pairs: [kh][i][op]
    __shared__ float sM[256];                // M[s][c] for this b
    __shared__ float sLN[16];                // scale[8], bias[8]
    __shared__ float sAnn[TTILE * 577];      // ann tile [t_loc][c*9 + o]

    int tid   = threadIdx.x;
    int b     = blockIdx.y;
    int t_blk = blockIdx.x * TTILE;

    const ull* Kg2 = (const ull*)Kg;
    for (int i = tid; i < 1024; i += 256) sK2[i] = Kg2[i];
    if (tid < 16) sLN[tid] = (tid < 8) ? lnS[tid] : lnB[tid - 8];
    {   // fold spatial_w into L_norm: one M element per thread
        int s = tid >> 6, m = tid & 63;
        const float* L = Ln + b * 4096;
        float acc = 0.f;
#pragma unroll 8
        for (int cc = 0; cc < 64; ++cc)
            acc += spw[cc * 4 + s] * L[cc * 64 + m];
        sM[s * 64 + m] = acc;
    }
    __syncthreads();

    int c = tid & 63;
    int g = tid >> 6;
    int t_first = t_blk + g * 4;
    const float* Xb = X + ((size_t)b * T_ * C_ + c) * F_;

    ull rw[4][8];                     // rolling window of 4 input rows (dup'd)
    ull acc[4][4];                    // [tt][op]  (op packs channels 2op,2op+1)
#pragma unroll
    for (int tt = 0; tt < 4; ++tt)
#pragma unroll
        for (int op = 0; op < 4; ++op) acc[tt][op] = 0ull;

#pragma unroll
    for (int slot = 0; slot < 4; ++slot) {
        int t_in = t_first - PAD_ + slot;
        if ((unsigned)t_in < (unsigned)T_) {
            const float4* p = (const float4*)(Xb + (size_t)t_in * C_ * F_);
            float4 a = p[0], q = p[1];
            rw[slot][0] = pack_dup(a.x); rw[slot][1] = pack_dup(a.y);
            rw[slot][2] = pack_dup(a.z); rw[slot][3] = pack_dup(a.w);
            rw[slot][4] = pack_dup(q.x); rw[slot][5] = pack_dup(q.y);
            rw[slot][6] = pack_dup(q.z); rw[slot][7] = pack_dup(q.w);
        } else {
#pragma unroll
            for (int i = 0; i < 8; ++i) rw[slot][i] = 0ull;
        }
    }

#pragma unroll 1
    for (int kh0 = 0; kh0 < 32; kh0 += 4) {
#pragma unroll
        for (int u = 0; u < 4; ++u) {
            int kh = kh0 + u;
            const ulonglong2* kp2 = (const ulonglong2*)(sK2 + kh * 32);
#pragma unroll
            for (int i = 0; i < 8; ++i) {
#pragma unroll
                for (int opp = 0; opp < 2; ++opp) {
                    ulonglong2 kk = kp2[i * 2 + opp];
#pragma unroll
                    for (int tt = 0; tt < 4; ++tt) {
                        ull x = rw[(u + tt) & 3][i];
                        acc[tt][2 * opp]     = fma2(x, kk.x, acc[tt][2 * opp]);
                        acc[tt][2 * opp + 1] = fma2(x, kk.y, acc[tt][2 * opp + 1]);
                    }
                }
            }
            if (kh < 31) {                        // refill slot u with row kh+4
                int t_in = t_first - PAD_ + kh + 4;
                if ((unsigned)t_in < (unsigned)T_) {
                    const float4* p = (const float4*)(Xb + (size_t)t_in * C_ * F_);
                    float4 a = p[0], q = p[1];
                    rw[u][0] = pack_dup(a.x); rw[u][1] = pack_dup(a.y);
                    rw[u][2] = pack_dup(a.z); rw[u][3] = pack_dup(a.w);
                    rw[u][4] = pack_dup(q.x); rw[u][5] = pack_dup(q.y);
                    rw[u][6] = pack_dup(q.z); rw[u][7] = pack_dup(q.w);
                } else {
#pragma unroll
                    for (int i = 0; i < 8; ++i) rw[u][i] = 0ull;
                }
            }
        }
    }

    // LayerNorm (eps 1e-6) + ReLU, write ann tile
#pragma unroll
    for (int tt = 0; tt < 4; ++tt) {
        float v[8];
#pragma unroll
        for (int op = 0; op < 4; ++op) unpack2(acc[tt][op], v[2 * op], v[2 * op + 1]);
        float mu = 0.f;
#pragma unroll
        for (int o = 0; o < 8; ++o) mu += v[o];
        mu *= 0.125f;
        float var = 0.f;
#pragma unroll
        for (int o = 0; o < 8; ++o) { float d = v[o] - mu; var += d * d; }
        var *= 0.125f;
        float inv = rsqrtf(var + 1e-6f);
        float* ap = sAnn + (g * 4 + tt) * 577 + c * 9;
#pragma unroll
        for (int o = 0; o < 8; ++o) {
            float a = (v[o] - mu) * inv * sLN[o] + sLN[8 + o];
            ap[o] = fmaxf(a, 0.f);
        }
    }
    __syncthreads();

    // projection: snn[b,t, s*8+f] = sum_c M[b,s,c] * ann[t,c,f]
    int tl      = tid >> 4;           // 0..15 local t
    int pairidx = tid & 15;
    int idx0    = pairidx * 2;        // even -> (idx0, idx0+1) share s
    int s       = idx0 >> 3;
    int f       = idx0 & 7;
    const float* mm = sM + s * 64;
    const float* ap = sAnn + tl * 577 + f;
    float a0 = 0.f, a1 = 0.f;
#pragma unroll 8
    for (int cc = 0; cc < 64; ++cc) {
        float mv = mm[cc];
        a0 += mv * ap[cc * 9];
        a1 += mv * ap[cc * 9 + 1];
    }
    float2* outp = (float2*)(g_snn + ((size_t)b * T_ + (t_blk + tl)) * 32 + idx0);
    *outp = make_float2(a0, a1);
}

// ---------------- K2: LIF scan + chunk means + head MLP + rate (fused) -----
// grid 64 (b), block 256. Warp 0 runs the sequential LIF recurrence with
// register double-buffered chunk loads into smem; all 8 warps then do the
// 3072x32 GEMV; warp 0 finishes GELU + logits. The last block to finish
// (atomic ticket) sums per-batch spike counts and writes the firing rate,
// then resets the ticket so graph replays start clean.
__global__ void __launch_bounds__(256)
k2_lif_head(const float* __restrict__ W1, const float* __restrict__ b1,
            const float* __restrict__ W2, const float* __restrict__ b2,
            float* __restrict__ out, int out_size) {
    __shared__ float sflat[3072];
    __shared__ float part[8][32];
    __shared__ float sy[32];

    int b   = blockIdx.x;
    int tid = threadIdx.x;

    if (tid < 32) {
        int j = tid;
        const float* p = g_snn + (size_t)b * T_ * 32 + j;
        float m1 = 0.f, m2 = 0.f, mo = 0.f;
        int cnt = 0;

        float cur[24], nxt[24];
#pragma unroll
        for (int r = 0; r < 24; ++r) cur[r] = p[r * 32];

        for (int k = 0; k < 48; ++k) {
            if (k < 47) {
                const float* pn = p + (size_t)(k + 1) * 24 * 32;
#pragma unroll
                for (int r = 0; r < 24; ++r) nxt[r] = pn[r * 32];
            }
            float sacc = 0.f, eacc = 0.f;
#pragma unroll
            for (int r = 0; r < 24; ++r) {
                float x = cur[r];
                m1 = m1 * 0.8f + x;
                float s1 = (m1 > 0.5f) ? 1.0f : 0.0f;
                m1 -= s1 * 0.5f;
                m2 = m2 * 0.9f + s1;
                float s2 = (m2 > 0.5f) ? 1.0f : 0.0f;
                m2 -= s2 * 0.5f;
                mo = mo * 0.95f + s2;
                cnt += (int)s1 + (int)s2;
                if (r < 12) sacc += mo; else eacc += mo;
            }
            sflat[k * 64 + j]      = sacc / 12.0f;
            sflat[k * 64 + 32 + j] = eacc / 12.0f;
#pragma unroll
            for (int r = 0; r < 24; ++r) cur[r] = nxt[r];
        }
#pragma unroll
        for (int off = 16; off; off >>= 1) cnt += __shfl_down_sync(0xffffffffu, cnt, off);
        if (j == 0) g_cnt[b] = cnt;
    }
    __syncthreads();

    // GEMV: y = flat @ W1 (+b1); 8 i-slices of 384, partials in smem
    {
        int j  = tid & 31;
        int sl = tid >> 5;            // 0..7
        const float* fb = sflat + sl * 384;
        const float* w  = W1 + (sl * 384) * 32 + j;
        float acc = 0.f;
#pragma unroll 8
        for (int i = 0; i < 384; ++i)
            acc += fb[i] * w[i * 32];
        part[sl][j] = acc;
    }
    __syncthreads();

    if (tid < 32) {
        float a = b1[tid];
#pragma unroll
        for (int s = 0; s < 8; ++s) a += part[s][tid];
        // jax.nn.gelu approximate=True (tanh form)
        float x  = a;
        float tn = tanhf(0.7978845608028654f * (x + 0.044715f * x * x * x));
        sy[tid]  = 0.5f * x * (1.0f + tn);
        __syncwarp();
        if (tid < 4) {
            float l = b2[tid];
#pragma unroll
            for (int jj = 0; jj < 32; ++jj) l += sy[jj] * W2[jj * 4 + tid];
            out[b * 4 + tid] = l;
        }
    }

    // firing-rate epilogue: last block sums deterministic per-batch counts
    __syncthreads();
    if (tid == 0) {
        __threadfence();
        int ticket = atomicAdd(&g_done, 1);
        if (ticket == B_ - 1) {
            __threadfence();
            int total = 0;
#pragma unroll 8
            for (int i = 0; i < B_; ++i) total += g_cnt[i];
            if (out_size > 256)
                out[256] = (float)((double)total /
                                   (2.0 * (double)B_ * (double)T_ * 32.0));
            g_done = 0;   // self-reset for next graph replay
        }
    }
}

// ---------------- launcher --------------------------------------------------
extern "C" void kernel_launch(void* const* d_in, const int* in_sizes, int n_in,
                              void* d_out, int out_size) {
    const float* Ln  = (const float*)d_in[0];   // L_norm  (B,C,C)
    const float* X   = (const float*)d_in[1];   // X_seq   (B,T,C,F)
    // d_in[2] = deterministic (unused)
    const float* Kg  = (const float*)d_in[3];   // conv_kernel (32,1,8,8)
    const float* lnS = (const float*)d_in[4];   // ln_scale (8)
    const float* lnB = (const float*)d_in[5];   // ln_bias  (8)
    const float* spw = (const float*)d_in[6];   // spatial_w (64,4)
    const float* W1  = (const float*)d_in[7];   // (3072,32)
    const float* b1  = (const float*)d_in[8];   // (32)
    const float* W2  = (const float*)d_in[9];   // (32,4)
    const float* b2  = (const float*)d_in[10];  // (4)
    float* out = (float*)d_out;

    dim3 g1(T_ / TTILE, B_);
    k1_conv<<<g1, 256>>>(X, Kg, lnS, lnB, Ln, spw);
    k2_lif_head<<<64, 256>>>(W1, b1, W2, b2, out, out_size);
}

// round 9
// speedup vs baseline: 1.0032x; 1.0032x over previous
#include <cuda_runtime.h>
#include <cstdint>

#define B_   64
#define T_   1152
#define C_   64
#define F_   8
#define KH_  32
#define PAD_ 15
#define TTILE 16

typedef unsigned long long ull;

// ---------------- scratch (device globals; no allocation allowed) ----------
__device__ float g_snn[(size_t)B_ * T_ * 32];           // snn_in (B,T,32)  ~9.4 MB
__device__ int   g_cnt[B_];                             // per-batch spike counts
__device__ int   g_done = 0;                            // completion ticket

// ---------------- f32x2 helpers (sm_100+) ----------------------------------
__device__ __forceinline__ ull pack_dup(float x) {
    unsigned int xi = __float_as_uint(x);
    ull r;
    asm("mov.b64 %0, {%1, %1};" : "=l"(r) : "r"(xi));
    return r;
}
__device__ __forceinline__ ull fma2(ull a, ull b, ull c) {
    ull d;
    asm("fma.rn.f32x2 %0, %1, %2, %3;" : "=l"(d) : "l"(a), "l"(b), "l"(c));
    return d;
}
__device__ __forceinline__ void unpack2(ull v, float& lo, float& hi) {
    unsigned int l, h;
    asm("mov.b64 {%0, %1}, %2;" : "=r"(l), "=r"(h) : "l"(v));
    lo = __uint_as_float(l);
    hi = __uint_as_float(h);
}

// ---------------- K1: conv(32 taps) + LN + ReLU + M-projection -------------
// grid (T/16, B), block 256: tid = c (0..63) + 64*g (g=0..3); each thread does
// 4 consecutive timesteps via a rolling 4-row register window (f32x2-dup'd).
// Invariant: at the start of tap kh, slot (r & 3) holds relative row r for
// r in [kh, kh+3]; output tt at tap kh consumes row kh+tt. Rows run to
// kh_max + tt_max = 34, hence refills continue while kh < 31.
// The folded projection matrix M[s][c] = sum_c' spw[c'][s] * L[b][c'][c] is
// computed in-block (one element per thread).
__global__ void __launch_bounds__(256)
k1_conv(const float* __restrict__ X, const float* __restrict__ Kg,
        const float* __restrict__ lnS, const float* __restrict__ lnB,
        const float* __restrict__ Ln, const float* __restrict__ spw) {
    __shared__ __align__(16) ull sK2[1024];  // conv kernel f32x2 pairs: [kh][i][op]
    __shared__ float sM[256];                // M[s][c] for this b
    __shared__ float sLN[16];                // scale[8], bias[8]
    __shared__ float sAnn[TTILE * 577];      // ann tile [t_loc][c*9 + o]

    int tid   = threadIdx.x;
    int b     = blockIdx.y;
    int t_blk = blockIdx.x * TTILE;

    const ull* Kg2 = (const ull*)Kg;
    for (int i = tid; i < 1024; i += 256) sK2[i] = Kg2[i];
    if (tid < 16) sLN[tid] = (tid < 8) ? lnS[tid] : lnB[tid - 8];
    {   // fold spatial_w into L_norm: one M element per thread
        int s = tid >> 6, m = tid & 63;
        const float* L = Ln + b * 4096;
        float acc = 0.f;
#pragma unroll 8
        for (int cc = 0; cc < 64; ++cc)
            acc += spw[cc * 4 + s] * L[cc * 64 + m];
        sM[s * 64 + m] = acc;
    }
    __syncthreads();

    int c = tid & 63;
    int g = tid >> 6;
    int t_first = t_blk + g * 4;
    const float* Xb = X + ((size_t)b * T_ * C_ + c) * F_;

    ull rw[4][8];                     // rolling window of 4 input rows (dup'd)
    ull acc[4][4];                    // [tt][op]  (op packs channels 2op,2op+1)
#pragma unroll
    for (int tt = 0; tt < 4; ++tt)
#pragma unroll
        for (int op = 0; op < 4; ++op) acc[tt][op] = 0ull;

#pragma unroll
    for (int slot = 0; slot < 4; ++slot) {
        int t_in = t_first - PAD_ + slot;
        if ((unsigned)t_in < (unsigned)T_) {
            const float4* p = (const float4*)(Xb + (size_t)t_in * C_ * F_);
            float4 a = p[0], q = p[1];
            rw[slot][0] = pack_dup(a.x); rw[slot][1] = pack_dup(a.y);
            rw[slot][2] = pack_dup(a.z); rw[slot][3] = pack_dup(a.w);
            rw[slot][4] = pack_dup(q.x); rw[slot][5] = pack_dup(q.y);
            rw[slot][6] = pack_dup(q.z); rw[slot][7] = pack_dup(q.w);
        } else {
#pragma unroll
            for (int i = 0; i < 8; ++i) rw[slot][i] = 0ull;
        }
    }

#pragma unroll 1
    for (int kh0 = 0; kh0 < 32; kh0 += 4) {
#pragma unroll
        for (int u = 0; u < 4; ++u) {
            int kh = kh0 + u;
            const ulonglong2* kp2 = (const ulonglong2*)(sK2 + kh * 32);
#pragma unroll
            for (int i = 0; i < 8; ++i) {
#pragma unroll
                for (int opp = 0; opp < 2; ++opp) {
                    ulonglong2 kk = kp2[i * 2 + opp];
#pragma unroll
                    for (int tt = 0; tt < 4; ++tt) {
                        ull x = rw[(u + tt) & 3][i];
                        acc[tt][2 * opp]     = fma2(x, kk.x, acc[tt][2 * opp]);
                        acc[tt][2 * opp + 1] = fma2(x, kk.y, acc[tt][2 * opp + 1]);
                    }
                }
            }
            if (kh < 31) {                        // refill slot u with row kh+4
                int t_in = t_first - PAD_ + kh + 4;
                if ((unsigned)t_in < (unsigned)T_) {
                    const float4* p = (const float4*)(Xb + (size_t)t_in * C_ * F_);
                    float4 a = p[0], q = p[1];
                    rw[u][0] = pack_dup(a.x); rw[u][1] = pack_dup(a.y);
                    rw[u][2] = pack_dup(a.z); rw[u][3] = pack_dup(a.w);
                    rw[u][4] = pack_dup(q.x); rw[u][5] = pack_dup(q.y);
                    rw[u][6] = pack_dup(q.z); rw[u][7] = pack_dup(q.w);
                } else {
#pragma unroll
                    for (int i = 0; i < 8; ++i) rw[u][i] = 0ull;
                }
            }
        }
    }

    // LayerNorm (eps 1e-6) + ReLU, write ann tile
#pragma unroll
    for (int tt = 0; tt < 4; ++tt) {
        float v[8];
#pragma unroll
        for (int op = 0; op < 4; ++op) unpack2(acc[tt][op], v[2 * op], v[2 * op + 1]);
        float mu = 0.f;
#pragma unroll
        for (int o = 0; o < 8; ++o) mu += v[o];
        mu *= 0.125f;
        float var = 0.f;
#pragma unroll
        for (int o = 0; o < 8; ++o) { float d = v[o] - mu; var += d * d; }
        var *= 0.125f;
        float inv = rsqrtf(var + 1e-6f);
        float* ap = sAnn + (g * 4 + tt) * 577 + c * 9;
#pragma unroll
        for (int o = 0; o < 8; ++o) {
            float a = (v[o] - mu) * inv * sLN[o] + sLN[8 + o];
            ap[o] = fmaxf(a, 0.f);
        }
    }
    __syncthreads();

    // projection: snn[b,t, s*8+f] = sum_c M[b,s,c] * ann[t,c,f]
    int tl      = tid >> 4;           // 0..15 local t
    int pairidx = tid & 15;
    int idx0    = pairidx * 2;        // even -> (idx0, idx0+1) share s
    int s       = idx0 >> 3;
    int f       = idx0 & 7;
    const float* mm = sM + s * 64;
    const float* ap = sAnn + tl * 577 + f;
    float a0 = 0.f, a1 = 0.f;
#pragma unroll 8
    for (int cc = 0; cc < 64; ++cc) {
        float mv = mm[cc];
        a0 += mv * ap[cc * 9];
        a1 += mv * ap[cc * 9 + 1];
    }
    float2* outp = (float2*)(g_snn + ((size_t)b * T_ + (t_blk + tl)) * 32 + idx0);
    *outp = make_float2(a0, a1);
}

// ---------------- K2: LIF scan + chunk means + head MLP + rate (fused) -----
// grid 64 (b), block 256. Warp 0 runs the sequential LIF recurrence with
// register double-buffered chunk loads into smem; all 8 warps then do the
// 3072x32 GEMV; warp 0 finishes GELU + logits. The last block to finish
// (atomic ticket) sums per-batch spike counts and writes the firing rate,
// then resets the ticket so graph replays start clean.
__global__ void __launch_bounds__(256)
k2_lif_head(const float* __restrict__ W1, const float* __restrict__ b1,
            const float* __restrict__ W2, const float* __restrict__ b2,
            float* __restrict__ out, int out_size) {
    __shared__ float sflat[3072];
    __shared__ float part[8][32];
    __shared__ float sy[32];

    int b   = blockIdx.x;
    int tid = threadIdx.x;

    if (tid < 32) {
        int j = tid;
        const float* p = g_snn + (size_t)b * T_ * 32 + j;
        float m1 = 0.f, m2 = 0.f, mo = 0.f;
        int cnt = 0;

        float cur[24], nxt[24];
#pragma unroll
        for (int r = 0; r < 24; ++r) cur[r] = p[r * 32];

        for (int k = 0; k < 48; ++k) {
            if (k < 47) {
                const float* pn = p + (size_t)(k + 1) * 24 * 32;
#pragma unroll
                for (int r = 0; r < 24; ++r) nxt[r] = pn[r * 32];
            }
            float sacc = 0.f, eacc = 0.f;
#pragma unroll
            for (int r = 0; r < 24; ++r) {
                float x = cur[r];
                m1 = m1 * 0.8f + x;
                float s1 = (m1 > 0.5f) ? 1.0f : 0.0f;
                m1 -= s1 * 0.5f;
                m2 = m2 * 0.9f + s1;
                float s2 = (m2 > 0.5f) ? 1.0f : 0.0f;
                m2 -= s2 * 0.5f;
                mo = mo * 0.95f + s2;
                cnt += (int)s1 + (int)s2;
                if (r < 12) sacc += mo; else eacc += mo;
            }
            sflat[k * 64 + j]      = sacc / 12.0f;
            sflat[k * 64 + 32 + j] = eacc / 12.0f;
#pragma unroll
            for (int r = 0; r < 24; ++r) cur[r] = nxt[r];
        }
#pragma unroll
        for (int off = 16; off; off >>= 1) cnt += __shfl_down_sync(0xffffffffu, cnt, off);
        if (j == 0) g_cnt[b] = cnt;
    }
    __syncthreads();

    // GEMV: y = flat @ W1 (+b1); 8 i-slices of 384, partials in smem
    {
        int j  = tid & 31;
        int sl = tid >> 5;            // 0..7
        const float* fb = sflat + sl * 384;
        const float* w  = W1 + (sl * 384) * 32 + j;
        float acc = 0.f;
#pragma unroll 8
        for (int i = 0; i < 384; ++i)
            acc += fb[i] * w[i * 32];
        part[sl][j] = acc;
    }
    __syncthreads();

    if (tid < 32) {
        float a = b1[tid];
#pragma unroll
        for (int s = 0; s < 8; ++s) a += part[s][tid];
        // jax.nn.gelu approximate=True (tanh form)
        float x  = a;
        float tn = tanhf(0.7978845608028654f * (x + 0.044715f * x * x * x));
        sy[tid]  = 0.5f * x * (1.0f + tn);
        __syncwarp();
        if (tid < 4) {
            float l = b2[tid];
#pragma unroll
            for (int jj = 0; jj < 32; ++jj) l += sy[jj] * W2[jj * 4 + tid];
            out[b * 4 + tid] = l;
        }
    }

    // firing-rate epilogue: last block sums deterministic per-batch counts
    __syncthreads();
    if (tid == 0) {
        __threadfence();
        int ticket = atomicAdd(&g_done, 1);
        if (ticket == B_ - 1) {
            __threadfence();
            int total = 0;
#pragma unroll 8
            for (int i = 0; i < B_; ++i) total += g_cnt[i];
            if (out_size > 256)
                out[256] = (float)((double)total /
                                   (2.0 * (double)B_ * (double)T_ * 32.0));
            g_done = 0;   // self-reset for next graph replay
        }
    }
}

// ---------------- launcher --------------------------------------------------
extern "C" void kernel_launch(void* const* d_in, const int* in_sizes, int n_in,
                              void* d_out, int out_size) {
    const float* Ln  = (const float*)d_in[0];   // L_norm  (B,C,C)
    const float* X   = (const float*)d_in[1];   // X_seq   (B,T,C,F)
    // d_in[2] = deterministic (unused)
    const float* Kg  = (const float*)d_in[3];   // conv_kernel (32,1,8,8)
    const float* lnS = (const float*)d_in[4];   // ln_scale (8)
    const float* lnB = (const float*)d_in[5];   // ln_bias  (8)
    const float* spw = (const float*)d_in[6];   // spatial_w (64,4)
    const float* W1  = (const float*)d_in[7];   // (3072,32)
    const float* b1  = (const float*)d_in[8];   // (32)
    const float* W2  = (const float*)d_in[9];   // (32,4)
    const float* b2  = (const float*)d_in[10];  // (4)
    float* out = (float*)d_out;

    dim3 g1(T_ / TTILE, B_);
    k1_conv<<<g1, 256>>>(X, Kg, lnS, lnB, Ln, spw);
    k2_lif_head<<<64, 256>>>(W1, b1, W2, b2, out, out_size);
}

// round 12
// speedup vs baseline: 1.0224x; 1.0191x over previous
#include <cuda_runtime.h>
#include <cstdint>

#define B_   64
#define T_   1152
#define C_   64
#define F_   8
#define KH_  32
#define PAD_ 15

typedef unsigned long long ull;

// ---------------- scratch (device globals; no allocation allowed) ----------
__device__ float g_M[B_ * 4 * C_];                      // folded spatial_w^T @ L_norm
__device__ float g_snn[(size_t)B_ * 32 * T_];           // snn_in TRANSPOSED (b,j,t)
__device__ int   g_cnt[B_];                             // per-batch spike counts
__device__ int   g_done = 0;                            // completion ticket

// ---------------- f32x2 helpers (sm_100+) ----------------------------------
__device__ __forceinline__ ull pack_dup(float x) {
    unsigned int xi = __float_as_uint(x);
    ull r;
    asm("mov.b64 %0, {%1, %1};" : "=l"(r) : "r"(xi));
    return r;
}
__device__ __forceinline__ ull fma2(ull a, ull b, ull c) {
    ull d;
    asm("fma.rn.f32x2 %0, %1, %2, %3;" : "=l"(d) : "l"(a), "l"(b), "l"(c));
    return d;
}
__device__ __forceinline__ void unpack2(ull v, float& lo, float& hi) {
    unsigned int l, h;
    asm("mov.b64 {%0, %1}, %2;" : "=r"(l), "=r"(h) : "l"(v));
    lo = __uint_as_float(l);
    hi = __uint_as_float(h);
}

// ---------------- K0: fold spatial_w into L_norm ----------------------------
__global__ void k0_prep(const float* __restrict__ Ln, const float* __restrict__ spw) {
    int b   = blockIdx.x;
    int tid = threadIdx.x;          // 256 threads: (s,m)
    int s = tid >> 6, m = tid & 63;
    const float* L = Ln + b * 4096;
    float acc = 0.f;
#pragma unroll 8
    for (int c = 0; c < 64; ++c)
        acc += spw[c * 4 + s] * L[c * 64 + m];
    g_M[b * 256 + s * 64 + m] = acc;
}

// ---------------- K1: conv(32 taps) + LN + ReLU + M-projection -------------
// grid (T/8, B), block 128: tid = c (0..63) + 64*g (g=0,1); each thread does
// 4 consecutive timesteps via a rolling 4-row register window (f32x2-dup'd).
// Invariant: at the start of tap kh, slot (r & 3) holds relative row r for
// r in [kh, kh+3]; output tt at tap kh consumes row kh+tt. Rows run to
// kh_max + tt_max = 34, hence refills continue while kh < 31.
// Output goes to the TRANSPOSED snn layout (b, j, t) via an smem staging
// tile so the global stores stay 32B-sector coalesced.
__global__ void __launch_bounds__(128)
k1_conv(const float* __restrict__ X, const float* __restrict__ Kg,
        const float* __restrict__ lnS, const float* __restrict__ lnB) {
    __shared__ __align__(16) ull sK2[1024];  // conv kernel f32x2 pairs: [kh][i][op]
    __shared__ float sM[256];                // M[s][c] for this b
    __shared__ float sLN[16];                // scale[8], bias[8]
    __shared__ float sAnn[8 * 577];          // ann tile [t_loc][c*9 + o]
    __shared__ float sOut[32 * 9];           // staged snn tile [j][tl], pad 9

    int tid   = threadIdx.x;
    int b     = blockIdx.y;
    int t_blk = blockIdx.x * 8;

    const ull* Kg2 = (const ull*)Kg;
    for (int i = tid; i < 1024; i += 128) sK2[i] = Kg2[i];
    for (int i = tid; i < 256;  i += 128) sM[i]  = g_M[b * 256 + i];
    if (tid < 8) { sLN[tid] = lnS[tid]; sLN[8 + tid] = lnB[tid]; }
    __syncthreads();

    int c = tid & 63;
    int g = tid >> 6;
    int t_first = t_blk + g * 4;
    const float* Xb = X + ((size_t)b * T_ * C_ + c) * F_;

    ull rw[4][8];                     // rolling window of 4 input rows (dup'd)
    ull acc[4][4];                    // [tt][op]  (op packs channels 2op,2op+1)
#pragma unroll
    for (int tt = 0; tt < 4; ++tt)
#pragma unroll
        for (int op = 0; op < 4; ++op) acc[tt][op] = 0ull;

#pragma unroll
    for (int slot = 0; slot < 4; ++slot) {
        int t_in = t_first - PAD_ + slot;
        if ((unsigned)t_in < (unsigned)T_) {
            const float4* p = (const float4*)(Xb + (size_t)t_in * C_ * F_);
            float4 a = p[0], q = p[1];
            rw[slot][0] = pack_dup(a.x); rw[slot][1] = pack_dup(a.y);
            rw[slot][2] = pack_dup(a.z); rw[slot][3] = pack_dup(a.w);
            rw[slot][4] = pack_dup(q.x); rw[slot][5] = pack_dup(q.y);
            rw[slot][6] = pack_dup(q.z); rw[slot][7] = pack_dup(q.w);
        } else {
#pragma unroll
            for (int i = 0; i < 8; ++i) rw[slot][i] = 0ull;
        }
    }

#pragma unroll 1
    for (int kh0 = 0; kh0 < 32; kh0 += 4) {
#pragma unroll
        for (int u = 0; u < 4; ++u) {
            int kh = kh0 + u;
            const ulonglong2* kp2 = (const ulonglong2*)(sK2 + kh * 32);
#pragma unroll
            for (int i = 0; i < 8; ++i) {
#pragma unroll
                for (int opp = 0; opp < 2; ++opp) {
                    ulonglong2 kk = kp2[i * 2 + opp];
#pragma unroll
                    for (int tt = 0; tt < 4; ++tt) {
                        ull x = rw[(u + tt) & 3][i];
                        acc[tt][2 * opp]     = fma2(x, kk.x, acc[tt][2 * opp]);
                        acc[tt][2 * opp + 1] = fma2(x, kk.y, acc[tt][2 * opp + 1]);
                    }
                }
            }
            if (kh < 31) {                        // refill slot u with row kh+4
                int t_in = t_first - PAD_ + kh + 4;
                if ((unsigned)t_in < (unsigned)T_) {
                    const float4* p = (const float4*)(Xb + (size_t)t_in * C_ * F_);
                    float4 a = p[0], q = p[1];
                    rw[u][0] = pack_dup(a.x); rw[u][1] = pack_dup(a.y);
                    rw[u][2] = pack_dup(a.z); rw[u][3] = pack_dup(a.w);
                    rw[u][4] = pack_dup(q.x); rw[u][5] = pack_dup(q.y);
                    rw[u][6] = pack_dup(q.z); rw[u][7] = pack_dup(q.w);
                } else {
#pragma unroll
                    for (int i = 0; i < 8; ++i) rw[u][i] = 0ull;
                }
            }
        }
    }

    // LayerNorm (eps 1e-6) + ReLU, write ann tile
#pragma unroll
    for (int tt = 0; tt < 4; ++tt) {
        float v[8];
#pragma unroll
        for (int op = 0; op < 4; ++op) unpack2(acc[tt][op], v[2 * op], v[2 * op + 1]);
        float mu = 0.f;
#pragma unroll
        for (int o = 0; o < 8; ++o) mu += v[o];
        mu *= 0.125f;
        float var = 0.f;
#pragma unroll
        for (int o = 0; o < 8; ++o) { float d = v[o] - mu; var += d * d; }
        var *= 0.125f;
        float inv = rsqrtf(var + 1e-6f);
        float* ap = sAnn + (g * 4 + tt) * 577 + c * 9;
#pragma unroll
        for (int o = 0; o < 8; ++o) {
            float a = (v[o] - mu) * inv * sLN[o] + sLN[8 + o];
            ap[o] = fmaxf(a, 0.f);
        }
    }
    __syncthreads();

    // projection: snn[b, j=s*8+f, t] = sum_c M[b,s,c] * ann[t,c,f]
    int tl      = tid >> 4;           // 0..7 local t
    int pairidx = tid & 15;
    int idx0    = pairidx * 2;        // even -> (idx0, idx0+1) share s
    int s       = idx0 >> 3;
    int f       = idx0 & 7;
    const float* mm = sM + s * 64;
    const float* ap = sAnn + tl * 577 + f;
    float a0 = 0.f, a1 = 0.f;
#pragma unroll 8
    for (int cc = 0; cc < 64; ++cc) {
        float mv = mm[cc];
        a0 += mv * ap[cc * 9];
        a1 += mv * ap[cc * 9 + 1];
    }
    sOut[idx0 * 9 + tl]       = a0;
    sOut[(idx0 + 1) * 9 + tl] = a1;
    __syncthreads();

    // coalesced transposed store: each thread writes rows j and j+16 at col t
    {
        int j = tid >> 3;             // 0..15
        int t = tid & 7;
        float v0 = sOut[j * 9 + t];
        float v1 = sOut[(j + 16) * 9 + t];
        g_snn[((size_t)b * 32 + j)      * T_ + t_blk + t] = v0;
        g_snn[((size_t)b * 32 + j + 16) * T_ + t_blk + t] = v1;
    }
}

// ---------------- K2: LIF scan + chunk means + head MLP + rate (fused) -----
// grid 64 (b), block 256. Warp 0 runs the sequential LIF recurrence; the
// transposed (b,j,t) layout makes each chain's series contiguous, so loads
// are LDG.128 (4 timesteps each). 12-step half-chunks double-buffered in
// 3x float4 (24 regs -> no spill); each half's ~300 cyc of serial LIF math
// covers the ~260 cyc L2 latency of the next half's 3 loads.
__global__ void __launch_bounds__(256)
k2_lif_head(const float* __restrict__ W1, const float* __restrict__ b1,
            const float* __restrict__ W2, const float* __restrict__ b2,
            float* __restrict__ out, int out_size) {
    __shared__ float sflat[3072];
    __shared__ float part[8][32];
    __shared__ float sy[32];

    int b   = blockIdx.x;
    int tid = threadIdx.x;

    if (tid < 32) {
        int j = tid;
        const float4* p4 = (const float4*)(g_snn + ((size_t)b * 32 + j) * T_);
        float m1 = 0.f, m2 = 0.f, mo = 0.f;
        int   cnt  = 0;
        float sacc = 0.f;

        float4 A0 = p4[0], A1 = p4[1], A2 = p4[2];

        for (int h = 0; h < 96; ++h) {           // 96 half-chunks of 12 steps
            int nb = (h < 95) ? (h + 1) * 3 : 0; // clamped prefetch index
            float4 B0 = p4[nb], B1 = p4[nb + 1], B2 = p4[nb + 2];

            float xs[12];
            xs[0] = A0.x; xs[1]  = A0.y; xs[2]  = A0.z; xs[3]  = A0.w;
            xs[4] = A1.x; xs[5]  = A1.y; xs[6]  = A1.z; xs[7]  = A1.w;
            xs[8] = A2.x; xs[9]  = A2.y; xs[10] = A2.z; xs[11] = A2.w;

            float hacc = 0.f;
#pragma unroll
            for (int r = 0; r < 12; ++r) {
                float x = xs[r];
                m1 = m1 * 0.8f + x;
                float s1 = (m1 > 0.5f) ? 1.0f : 0.0f;
                m1 -= s1 * 0.5f;
                m2 = m2 * 0.9f + s1;
                float s2 = (m2 > 0.5f) ? 1.0f : 0.0f;
                m2 -= s2 * 0.5f;
                mo = mo * 0.95f + s2;
                cnt += (int)s1 + (int)s2;
                hacc += mo;
            }
            if ((h & 1) == 0) {
                sacc = hacc;
            } else {
                int k = h >> 1;
                sflat[k * 64 + j]      = sacc / 12.0f;
                sflat[k * 64 + 32 + j] = hacc / 12.0f;
            }
            A0 = B0; A1 = B1; A2 = B2;
        }
#pragma unroll
        for (int off = 16; off; off >>= 1) cnt += __shfl_down_sync(0xffffffffu, cnt, off);
        if (j == 0) g_cnt[b] = cnt;
    }
    __syncthreads();

    // GEMV: y = flat @ W1 (+b1); 8 i-slices of 384, partials in smem
    {
        int j  = tid & 31;
        int sl = tid >> 5;            // 0..7
        const float* fb = sflat + sl * 384;
        const float* w  = W1 + (sl * 384) * 32 + j;
        float acc = 0.f;
#pragma unroll 8
        for (int i = 0; i < 384; ++i)
            acc += fb[i] * w[i * 32];
        part[sl][j] = acc;
    }
    __syncthreads();

    if (tid < 32) {
        float a = b1[tid];
#pragma unroll
        for (int s = 0; s < 8; ++s) a += part[s][tid];
        // jax.nn.gelu approximate=True (tanh form)
        float x  = a;
        float tn = tanhf(0.7978845608028654f * (x + 0.044715f * x * x * x));
        sy[tid]  = 0.5f * x * (1.0f + tn);
        __syncwarp();
        if (tid < 4) {
            float l = b2[tid];
#pragma unroll
            for (int jj = 0; jj < 32; ++jj) l += sy[jj] * W2[jj * 4 + tid];
            out[b * 4 + tid] = l;
        }
    }

    // firing-rate epilogue: last block sums deterministic per-batch counts
    __syncthreads();
    if (tid == 0) {
        __threadfence();
        int ticket = atomicAdd(&g_done, 1);
        if (ticket == B_ - 1) {
            __threadfence();
            int total = 0;
#pragma unroll 8
            for (int i = 0; i < B_; ++i) total += g_cnt[i];
            if (out_size > 256)
                out[256] = (float)((double)total /
                                   (2.0 * (double)B_ * (double)T_ * 32.0));
            g_done = 0;   // self-reset for next graph replay
        }
    }
}

// ---------------- launcher --------------------------------------------------
extern "C" void kernel_launch(void* const* d_in, const int* in_sizes, int n_in,
                              void* d_out, int out_size) {
    const float* Ln  = (const float*)d_in[0];   // L_norm  (B,C,C)
    const float* X   = (const float*)d_in[1];   // X_seq   (B,T,C,F)
    // d_in[2] = deterministic (unused)
    const float* Kg  = (const float*)d_in[3];   // conv_kernel (32,1,8,8)
    const float* lnS = (const float*)d_in[4];   // ln_scale (8)
    const float* lnB = (const float*)d_in[5];   // ln_bias  (8)
    const float* spw = (const float*)d_in[6];   // spatial_w (64,4)
    const float* W1  = (const float*)d_in[7];   // (3072,32)
    const float* b1  = (const float*)d_in[8];   // (32)
    const float* W2  = (const float*)d_in[9];   // (32,4)
    const float* b2  = (const float*)d_in[10];  // (4)
    float* out = (float*)d_out;

    k0_prep<<<64, 256>>>(Ln, spw);
    dim3 g1(T_ / 8, B_);
    k1_conv<<<g1, 128>>>(X, Kg, lnS, lnB);
    k2_lif_head<<<64, 256>>>(W1, b1, W2, b2, out, out_size);
}